// round 13
// baseline (speedup 1.0000x reference)
#include <cuda_runtime.h>
#include <math.h>
#include <stdint.h>

#define NL 1024
#define NB 64
#define NH 512
#define NP 21
#define NLU 60
#define NCTA_LSTM 128
#define SMEM_LSTM 206976

// ---------------- device scratch (static, no allocation) ----------------
__device__ float4 d_E4[2 * 20 * NH];           // [dir][sym][unit] -> 4 gate pre-acts (bias folded)
__device__ float4 d_gh[2][2][128 * 64];        // [buf][dir][kq*64+b] h in k-quad float4 layout
__device__ float  d_hs[(size_t)NL * NB * 1024];// [l][b][dir*512+j]
__device__ float  d_phi[NL * NB * 3];
__device__ float  d_tab[NLU * 6];              // [u][c][{sin,cos}]
__device__ unsigned g_cnt;
__device__ unsigned g_gen;

__device__ __forceinline__ float sigf(float x) { return 1.f / (1.f + expf(-x)); }

// ---------------- init: zero h buffers, reset barrier, sin/cos table ----------------
__global__ void k_init(const float* __restrict__ alphabet) {
    int idx = blockIdx.x * 256 + threadIdx.x;
    float4* g = &d_gh[0][0][0];
    if (idx < 2 * 2 * 128 * 64) g[idx] = make_float4(0.f, 0.f, 0.f, 0.f);
    if (idx == 0) { g_cnt = 0u; g_gen = 0u; }
    if (idx < NLU) {
        #pragma unroll
        for (int c = 0; c < 3; c++) {
            float s, co;
            sincosf(alphabet[idx * 3 + c], &s, &co);
            d_tab[idx * 6 + c * 2 + 0] = s;
            d_tab[idx * 6 + c * 2 + 1] = co;
        }
    }
}

// ---------------- E table: E4[d][s][j].q = embed[s] . Wih_d[q*512+j, :512] + bias ----------------
__global__ void k_embed(const float* __restrict__ embed,
                        const float* __restrict__ Wih_f, const float* __restrict__ bih_f, const float* __restrict__ bhh_f,
                        const float* __restrict__ Wih_b, const float* __restrict__ bih_b, const float* __restrict__ bhh_b) {
    int w = (blockIdx.x * blockDim.x + threadIdx.x) >> 5;  // 4096 gate rows
    int lane = threadIdx.x & 31;
    if (w >= 4096) return;
    int d = w >> 11, g = w & 2047, q = g >> 9, j = g & 511;
    const float* Wih = d ? Wih_b : Wih_f;
    float bias = d ? (bih_b[g] + bhh_b[g]) : (bih_f[g] + bhh_f[g]);
    const float* wrow = Wih + (size_t)g * 533;
    float wr[16];
    #pragma unroll
    for (int i = 0; i < 16; i++) wr[i] = wrow[lane + i * 32];
    for (int s = 0; s < 20; s++) {
        const float* er = embed + s * 512;
        float acc = 0.f;
        #pragma unroll
        for (int i = 0; i < 16; i++) acc += er[lane + i * 32] * wr[i];
        #pragma unroll
        for (int o = 16; o; o >>= 1) acc += __shfl_xor_sync(0xffffffffu, acc, o);
        if (lane == 0)
            ((float*)d_E4)[(((d * 20 + s) * 512) + j) * 4 + q] = acc + bias;
    }
}

// ---------------- grid barrier (all 128 CTAs resident, 1/SM) ----------------
__device__ __forceinline__ void gridBarrier(int r) {
    __syncthreads();
    if (threadIdx.x == 0) {
        __threadfence();
        if (atomicAdd(&g_cnt, 1u) == NCTA_LSTM - 1) {
            atomicExch(&g_cnt, 0u);
            __threadfence();
            atomicAdd(&g_gen, 1u);
        } else {
            volatile unsigned* vg = &g_gen;
            while (*vg < (unsigned)(r + 1)) {}
        }
        __threadfence();
    }
    __syncthreads();
}

// ---------------- persistent biLSTM: CTA = {dir, 8 units}, warp = 1 unit, lane = 2 batches ----------------
__global__ void __launch_bounds__(256, 1) k_lstm(
    const int* __restrict__ seq, const float* __restrict__ pssm,
    const float* __restrict__ Wih_f, const float* __restrict__ Whh_f,
    const float* __restrict__ Wih_b, const float* __restrict__ Whh_b)
{
    extern __shared__ float smf[];
    float4* Wsm = (float4*)smf;            // [8 u][128 kq][4 gates]   4096 f4 (64KB)
    float4* hQ  = Wsm + 4096;              // [128 kq][64 b]           8192 f4 (128KB)
    float*  psm = (float*)(hQ + 8192);     // [64 b][21]               1408 fl
    float4* Wp  = (float4*)(psm + 1408);   // [8 u][21]                168 f4
    float*  h8  = (float*)(Wp + 168);      // [64 b][8 u]              512 fl

    const int tid = threadIdx.x;
    const int dir = blockIdx.x >> 6;
    const int ub  = blockIdx.x & 63;
    const float* Whh = dir ? Whh_b : Whh_f;
    const float* Wih = dir ? Wih_b : Wih_f;

    // stage Whh slice: Wsm[u][kq][q] = Whh[q*512+ub*8+u][4kq..4kq+3]
    for (int s = tid; s < 4096; s += 256) {
        int u = s >> 9, rest = s & 511, kq = rest >> 2, q = rest & 3;
        int row = q * 512 + ub * 8 + u;
        Wsm[s] = *((const float4*)(Whh + (size_t)row * 512) + kq);
    }
    // stage pssm part of Wih: Wp[u][jj].q = Wih[q*512+j][512+jj]
    for (int s = tid; s < 672; s += 256) {
        int u = s / 84, rr = s % 84, jj = rr >> 2, q = rr & 3;
        ((float*)Wp)[(u * 21 + jj) * 4 + q] =
            Wih[(size_t)(q * 512 + ub * 8 + u) * 533 + 512 + jj];
    }

    const int u = tid >> 5, lane = tid & 31;
    const int j = ub * 8 + u;
    float c0 = 0.f, c1 = 0.f;

    for (int r = 0; r < NL; r++) {
        const int t = dir ? (NL - 1 - r) : r;
        const int rb = r & 1;

        // stage h (128KB, L2 broadcast) and pssm row
        const float4* src = d_gh[rb][dir];
        #pragma unroll
        for (int i = 0; i < 32; i++)
            hQ[tid + i * 256] = __ldcg(src + tid + i * 256);
        for (int i = tid; i < NB * NP; i += 256)
            psm[i] = pssm[t * NB * NP + i];
        __syncthreads();

        // z init from E table (input GEMM + bias folded)
        int s0 = seq[t * NB + lane];
        int s1 = seq[t * NB + lane + 32];
        float4 e0 = d_E4[(dir * 20 + s0) * 512 + j];
        float4 e1 = d_E4[(dir * 20 + s1) * 512 + j];
        float z0 = e0.x, z1 = e0.y, z2 = e0.z, z3 = e0.w;
        float z4 = e1.x, z5 = e1.y, z6 = e1.z, z7 = e1.w;

        // pssm contribution (21 dims)
        #pragma unroll
        for (int jj = 0; jj < NP; jj++) {
            float4 w = Wp[u * 21 + jj];
            float p0 = psm[lane * 21 + jj];
            float p1 = psm[(lane + 32) * 21 + jj];
            z0 += w.x * p0; z1 += w.y * p0; z2 += w.z * p0; z3 += w.w * p0;
            z4 += w.x * p1; z5 += w.y * p1; z6 += w.z * p1; z7 += w.w * p1;
        }

        // recurrent GEMM: 128 k-quads over H=512
        const float4* Wu = Wsm + (u << 9);
        #pragma unroll 4
        for (int kq = 0; kq < 128; kq++) {
            float4 ha = hQ[(kq << 6) + lane];
            float4 hb = hQ[(kq << 6) + lane + 32];
            float4 w0 = Wu[(kq << 2) + 0];
            float4 w1 = Wu[(kq << 2) + 1];
            float4 w2 = Wu[(kq << 2) + 2];
            float4 w3 = Wu[(kq << 2) + 3];
            z0 += w0.x * ha.x; z0 += w0.y * ha.y; z0 += w0.z * ha.z; z0 += w0.w * ha.w;
            z1 += w1.x * ha.x; z1 += w1.y * ha.y; z1 += w1.z * ha.z; z1 += w1.w * ha.w;
            z2 += w2.x * ha.x; z2 += w2.y * ha.y; z2 += w2.z * ha.z; z2 += w2.w * ha.w;
            z3 += w3.x * ha.x; z3 += w3.y * ha.y; z3 += w3.z * ha.z; z3 += w3.w * ha.w;
            z4 += w0.x * hb.x; z4 += w0.y * hb.y; z4 += w0.z * hb.z; z4 += w0.w * hb.w;
            z5 += w1.x * hb.x; z5 += w1.y * hb.y; z5 += w1.z * hb.z; z5 += w1.w * hb.w;
            z6 += w2.x * hb.x; z6 += w2.y * hb.y; z6 += w2.z * hb.z; z6 += w2.w * hb.w;
            z7 += w3.x * hb.x; z7 += w3.y * hb.y; z7 += w3.z * hb.z; z7 += w3.w * hb.w;
        }

        // gates (torch order i,f,g,o)
        float i0 = sigf(z0), f0 = sigf(z1), gg0 = tanhf(z2), o0 = sigf(z3);
        c0 = f0 * c0 + i0 * gg0;
        float hh0 = o0 * tanhf(c0);
        float i1 = sigf(z4), f1 = sigf(z5), gg1 = tanhf(z6), o1 = sigf(z7);
        c1 = f1 * c1 + i1 * gg1;
        float hh1 = o1 * tanhf(c1);

        // publish h for next step (ping-pong, k-quad layout)
        float* gw = (float*)(d_gh[rb ^ 1][dir]);
        gw[(((j >> 2) << 6) + lane) * 4 + (j & 3)]      = hh0;
        gw[(((j >> 2) << 6) + lane + 32) * 4 + (j & 3)] = hh1;

        // gather into smem -> contiguous history write for k_logits
        h8[lane * 8 + u]        = hh0;
        h8[(lane + 32) * 8 + u] = hh1;
        __syncthreads();
        {
            int v0 = tid, v1 = tid + 256;
            d_hs[(size_t)(t * 64 + (v0 >> 3)) * 1024 + dir * 512 + ub * 8 + (v0 & 7)] = h8[v0];
            d_hs[(size_t)(t * 64 + (v1 >> 3)) * 1024 + dir * 512 + ub * 8 + (v1 & 7)] = h8[v1];
        }

        gridBarrier(r);
    }
}

// ---------------- logits + softmax + angularization (warp per (l,b) row) ----------------
__global__ void __launch_bounds__(256) k_logits(const float* __restrict__ W_lin,
                                                const float* __restrict__ b_lin) {
    __shared__ float lg[8][64];
    int w = threadIdx.x >> 5, lane = threadIdx.x & 31;
    int row = blockIdx.x * 8 + w;  // l*64 + b
    const float4* hv = (const float4*)(d_hs + (size_t)row * 1024);
    float4 h4[8];
    #pragma unroll
    for (int i = 0; i < 8; i++) h4[i] = hv[i * 32 + lane];

    for (int uu = 0; uu < NLU; uu++) {
        const float4* wl = (const float4*)(W_lin + uu * 1024);
        float acc = 0.f;
        #pragma unroll
        for (int i = 0; i < 8; i++) {
            float4 wv = __ldg(wl + i * 32 + lane);
            acc += h4[i].x * wv.x + h4[i].y * wv.y + h4[i].z * wv.z + h4[i].w * wv.w;
        }
        #pragma unroll
        for (int o = 16; o; o >>= 1) acc += __shfl_xor_sync(0xffffffffu, acc, o);
        if (lane == 0) lg[w][uu] = acc + b_lin[uu];
    }
    __syncwarp();

    float a0 = lg[w][lane];
    float a1 = (lane < 28) ? lg[w][lane + 32] : -3.4e38f;
    float m = fmaxf(a0, a1);
    #pragma unroll
    for (int o = 16; o; o >>= 1) m = fmaxf(m, __shfl_xor_sync(0xffffffffu, m, o));
    float e0 = expf(a0 - m);
    float e1 = (lane < 28) ? expf(a1 - m) : 0.f;
    float s = e0 + e1;
    #pragma unroll
    for (int o = 16; o; o >>= 1) s += __shfl_xor_sync(0xffffffffu, s, o);
    float p0 = e0 / s, p1 = e1 / s;

    int u1 = (lane < 28) ? lane + 32 : 0;
    const float* t0 = d_tab + lane * 6;
    const float* t1 = d_tab + u1 * 6;
    float sA = p0 * t0[0] + p1 * t1[0], cA = p0 * t0[1] + p1 * t1[1];
    float sB = p0 * t0[2] + p1 * t1[2], cB = p0 * t0[3] + p1 * t1[3];
    float sC = p0 * t0[4] + p1 * t1[4], cC = p0 * t0[5] + p1 * t1[5];
    #pragma unroll
    for (int o = 16; o; o >>= 1) {
        sA += __shfl_xor_sync(0xffffffffu, sA, o);
        cA += __shfl_xor_sync(0xffffffffu, cA, o);
        sB += __shfl_xor_sync(0xffffffffu, sB, o);
        cB += __shfl_xor_sync(0xffffffffu, cB, o);
        sC += __shfl_xor_sync(0xffffffffu, sC, o);
        cC += __shfl_xor_sync(0xffffffffu, cC, o);
    }
    if (lane == 0) {
        d_phi[row * 3 + 0] = atan2f(sA, cA);
        d_phi[row * 3 + 1] = atan2f(sB, cB);
        d_phi[row * 3 + 2] = atan2f(sC, cC);
    }
}

// ---------------- NeRF chain extension (thread per batch) ----------------
__global__ void k_geom(float* __restrict__ out) {
    int b = threadIdx.x;
    if (b >= NB) return;
    const float BL[3] = {132.868f, 145.801f, 152.326f};
    const float BA[3] = {2.028f, 2.124f, 1.941f};
    float cT[3], sT[3];
    #pragma unroll
    for (int jj = 0; jj < 3; jj++) sincosf(BA[jj], &sT[jj], &cT[jj]);

    float Ax = 1.f, Ay = 0.f, Az = 0.f;
    float Bx = 0.f, By = 1.f, Bz = 0.f;
    float Cx = 0.f, Cy = 0.f, Cz = 1.f;
    #pragma unroll
    for (int r = 0; r < 3; r++)
        #pragma unroll
        for (int c = 0; c < 3; c++)
            out[((size_t)r * 64 + b) * 3 + c] = (r == c) ? 1.f : 0.f;

    for (int i = 0; i < NL; i++) {
        #pragma unroll
        for (int jj = 0; jj < 3; jj++) {
            float P = d_phi[((size_t)i * 64 + b) * 3 + jj];
            float sp, cp;
            sincosf(P, &sp, &cp);
            float D2x = -BL[jj] * cT[jj];
            float D2y =  BL[jj] * cp * sT[jj];
            float D2z =  BL[jj] * sp * sT[jj];
            float bcx = Cx - Bx, bcy = Cy - By, bcz = Cz - Bz;
            float il = 1.f / sqrtf(bcx * bcx + bcy * bcy + bcz * bcz);
            bcx *= il; bcy *= il; bcz *= il;
            float abx = Bx - Ax, aby = By - Ay, abz = Bz - Az;
            float nx = aby * bcz - abz * bcy;
            float ny = abz * bcx - abx * bcz;
            float nz = abx * bcy - aby * bcx;
            float iln = 1.f / sqrtf(nx * nx + ny * ny + nz * nz);
            nx *= iln; ny *= iln; nz *= iln;
            float mx = ny * bcz - nz * bcy;
            float my = nz * bcx - nx * bcz;
            float mz = nx * bcy - ny * bcx;
            float Dx = D2x * bcx + D2y * mx + D2z * nx + Cx;
            float Dy = D2x * bcy + D2y * my + D2z * ny + Cy;
            float Dz = D2x * bcz + D2y * mz + D2z * nz + Cz;
            size_t rw = (size_t)(3 + i * 3 + jj) * 64 + b;
            out[rw * 3 + 0] = Dx; out[rw * 3 + 1] = Dy; out[rw * 3 + 2] = Dz;
            Ax = Bx; Ay = By; Az = Bz;
            Bx = Cx; By = Cy; Bz = Cz;
            Cx = Dx; Cy = Dy; Cz = Dz;
        }
    }
}

extern "C" void kernel_launch(void* const* d_in, const int* in_sizes, int n_in,
                              void* d_out, int out_size) {
    const int*   seq      = (const int*)d_in[0];
    const float* pssm     = (const float*)d_in[1];
    // d_in[2] = length (unused: all full-length)
    const float* embed    = (const float*)d_in[3];
    const float* Wih_f    = (const float*)d_in[4];
    const float* Whh_f    = (const float*)d_in[5];
    const float* bih_f    = (const float*)d_in[6];
    const float* bhh_f    = (const float*)d_in[7];
    const float* Wih_b    = (const float*)d_in[8];
    const float* Whh_b    = (const float*)d_in[9];
    const float* bih_b    = (const float*)d_in[10];
    const float* bhh_b    = (const float*)d_in[11];
    const float* W_lin    = (const float*)d_in[12];
    const float* b_lin    = (const float*)d_in[13];
    const float* alphabet = (const float*)d_in[14];
    float* out = (float*)d_out;

    cudaFuncSetAttribute(k_lstm, cudaFuncAttributeMaxDynamicSharedMemorySize, SMEM_LSTM);

    k_init<<<128, 256>>>(alphabet);
    k_embed<<<512, 256>>>(embed, Wih_f, bih_f, bhh_f, Wih_b, bih_b, bhh_b);
    k_lstm<<<NCTA_LSTM, 256, SMEM_LSTM>>>(seq, pssm, Wih_f, Whh_f, Wih_b, Whh_b);
    k_logits<<<NL * NB / 8, 256>>>(W_lin, b_lin);
    k_geom<<<1, 64>>>(out);
}

// round 14
// speedup vs baseline: 1.2532x; 1.2532x over previous
#include <cuda_runtime.h>
#include <math.h>
#include <stdint.h>

#define NL 1024
#define NB 64
#define NH 512
#define NP 21
#define NLU 60
#define NCTA_LSTM 128
#define SMEM_LSTM 207104

typedef unsigned long long ull;

// ---------------- device scratch (static, no allocation) ----------------
__device__ float4 d_E4[2 * 20 * NH];           // [dir][sym][unit] -> 4 gate pre-acts (bias folded)
__device__ float4 d_gh[2][2][128 * 64];        // [buf][dir][kq*64+b] h in k-quad float4 layout
__device__ float  d_hs[(size_t)NL * NB * 1024];// [l][b][dir*512+j]
__device__ float  d_phi[NL * NB * 3];
__device__ float  d_tab[NLU * 6];              // [u][c][{sin,cos}]
__device__ unsigned g_cnt;
__device__ unsigned g_gen;

__device__ __forceinline__ float sigf(float x) { return 1.f / (1.f + expf(-x)); }

__device__ __forceinline__ ull pk2(float lo, float hi) {
    ull r; asm("mov.b64 %0, {%1, %2};" : "=l"(r) : "f"(lo), "f"(hi)); return r;
}
__device__ __forceinline__ float2 upk2(ull v) {
    float2 f; asm("mov.b64 {%0, %1}, %2;" : "=f"(f.x), "=f"(f.y) : "l"(v)); return f;
}
#define FMA2(d, a, b) asm("fma.rn.f32x2 %0, %1, %2, %0;" : "+l"(d) : "l"(a), "l"(b))

// ---------------- init: zero h buffers, reset barrier, sin/cos table ----------------
__global__ void k_init(const float* __restrict__ alphabet) {
    int idx = blockIdx.x * 256 + threadIdx.x;
    float4* g = &d_gh[0][0][0];
    if (idx < 2 * 2 * 128 * 64) g[idx] = make_float4(0.f, 0.f, 0.f, 0.f);
    if (idx == 0) { g_cnt = 0u; g_gen = 0u; }
    if (idx < NLU) {
        #pragma unroll
        for (int c = 0; c < 3; c++) {
            float s, co;
            sincosf(alphabet[idx * 3 + c], &s, &co);
            d_tab[idx * 6 + c * 2 + 0] = s;
            d_tab[idx * 6 + c * 2 + 1] = co;
        }
    }
}

// ---------------- E table: E4[d][s][j].q = embed[s] . Wih_d[q*512+j, :512] + bias ----------------
__global__ void k_embed(const float* __restrict__ embed,
                        const float* __restrict__ Wih_f, const float* __restrict__ bih_f, const float* __restrict__ bhh_f,
                        const float* __restrict__ Wih_b, const float* __restrict__ bih_b, const float* __restrict__ bhh_b) {
    int w = (blockIdx.x * blockDim.x + threadIdx.x) >> 5;  // 4096 gate rows
    int lane = threadIdx.x & 31;
    if (w >= 4096) return;
    int d = w >> 11, g = w & 2047, q = g >> 9, j = g & 511;
    const float* Wih = d ? Wih_b : Wih_f;
    float bias = d ? (bih_b[g] + bhh_b[g]) : (bih_f[g] + bhh_f[g]);
    const float* wrow = Wih + (size_t)g * 533;
    float wr[16];
    #pragma unroll
    for (int i = 0; i < 16; i++) wr[i] = wrow[lane + i * 32];
    for (int s = 0; s < 20; s++) {
        const float* er = embed + s * 512;
        float acc = 0.f;
        #pragma unroll
        for (int i = 0; i < 16; i++) acc += er[lane + i * 32] * wr[i];
        #pragma unroll
        for (int o = 16; o; o >>= 1) acc += __shfl_xor_sync(0xffffffffu, acc, o);
        if (lane == 0)
            ((float*)d_E4)[(((d * 20 + s) * 512) + j) * 4 + q] = acc + bias;
    }
}

// ---------------- grid barrier (all 128 CTAs resident, 1/SM) ----------------
__device__ __forceinline__ void gridBarrier(int r) {
    __syncthreads();
    if (threadIdx.x == 0) {
        __threadfence();
        if (atomicAdd(&g_cnt, 1u) == NCTA_LSTM - 1) {
            atomicExch(&g_cnt, 0u);
            __threadfence();
            atomicAdd(&g_gen, 1u);
        } else {
            volatile unsigned* vg = &g_gen;
            while (*vg < (unsigned)(r + 1)) {}
        }
        __threadfence();
    }
    __syncthreads();
}

// ---------------- persistent biLSTM: CTA = {dir, 8 units}, warp = 2 units, lane = 2 batches ----------------
__global__ void __launch_bounds__(128, 1) k_lstm(
    const int* __restrict__ seq, const float* __restrict__ pssm,
    const float* __restrict__ Whh_f, const float* __restrict__ Whh_b,
    const float* __restrict__ Wih_f, const float* __restrict__ Wih_b)
{
    extern __shared__ float smf[];
    float4* Wsm  = (float4*)smf;           // [8 u][128 kq][4 q]    4096 f4 (64KB)
    float4* hQ   = Wsm + 4096;             // [128 kq][64 b]        8192 f4 (128KB)
    float*  psmF = (float*)(hQ + 8192);    // [64 b][22]            1408 fl
    float*  WpF  = psmF + 1408;            // [8 u][4 q][22]        704 fl
    float*  h8   = WpF + 704;              // [64 b][8 u]           512 fl

    const int tid = threadIdx.x;
    const int dir = blockIdx.x >> 6;
    const int ub  = blockIdx.x & 63;
    const float* Whh = dir ? Whh_b : Whh_f;
    const float* Wih = dir ? Wih_b : Wih_f;

    // one-time: Whh slice  Wsm[u*512 + kq*4 + q] = Whh[q*512+ub*8+u][4kq..4kq+3]
    for (int s = tid; s < 4096; s += 128) {
        int u = s >> 9, kq = (s >> 2) & 127, q = s & 3;
        Wsm[s] = *((const float4*)(Whh + (size_t)(q * 512 + ub * 8 + u) * 512) + kq);
    }
    // one-time: pssm weights  WpF[(u*4+q)*22 + jj], jj padded to 22 with 0
    for (int s = tid; s < 672; s += 128) {
        int u = s / 84, rr = s % 84, q = rr / 21, jj = rr % 21;
        WpF[(u * 4 + q) * 22 + jj] = Wih[(size_t)(q * 512 + ub * 8 + u) * 533 + 512 + jj];
    }
    if (tid < 32) WpF[tid * 22 + 21] = 0.f;
    if (tid < 64) psmF[tid * 22 + 21] = 0.f;   // pad, never overwritten

    const int w = tid >> 5, lane = tid & 31;
    const int uw = w * 2;             // local units uw, uw+1
    const int j0 = ub * 8 + uw;
    float cst[2][2] = {{0.f, 0.f}, {0.f, 0.f}};
    uint32_t hq_s = (uint32_t)__cvta_generic_to_shared(hQ);

    for (int r = 0; r < NL; r++) {
        const int t = dir ? (NL - 1 - r) : r;
        const int rb = r & 1;
        const float4* src = d_gh[rb][dir];

        // async-stage h in 4 groups of 32 kq (32KB each)
        #pragma unroll
        for (int g = 0; g < 4; g++) {
            #pragma unroll
            for (int i = 0; i < 16; i++) {
                int idx = tid + (g * 16 + i) * 128;
                asm volatile("cp.async.cg.shared.global [%0], [%1], 16;"
                             :: "r"(hq_s + idx * 16), "l"(src + idx) : "memory");
            }
            asm volatile("cp.async.commit_group;" ::: "memory");
        }

        // stage pssm row (thread pair per batch)
        {
            int b = tid >> 1, hf = tid & 1;
            const float* prow = pssm + (size_t)t * (NB * NP) + b * NP;
            if (hf == 0) {
                #pragma unroll
                for (int jj = 0; jj < 11; jj++) psmF[b * 22 + jj] = prow[jj];
            } else {
                #pragma unroll
                for (int jj = 11; jj < 21; jj++) psmF[b * 22 + jj] = prow[jj];
            }
        }

        // init accumulators from E table (input GEMM + bias folded; lo lane only)
        int s0 = seq[t * NB + lane];
        int s1 = seq[t * NB + 32 + lane];
        float4 eA0 = d_E4[(dir * 20 + s0) * 512 + j0];
        float4 eA1 = d_E4[(dir * 20 + s0) * 512 + j0 + 1];
        float4 eB0 = d_E4[(dir * 20 + s1) * 512 + j0];
        float4 eB1 = d_E4[(dir * 20 + s1) * 512 + j0 + 1];
        ull acc[2][4][2];
        acc[0][0][0] = pk2(eA0.x, 0.f); acc[0][1][0] = pk2(eA0.y, 0.f);
        acc[0][2][0] = pk2(eA0.z, 0.f); acc[0][3][0] = pk2(eA0.w, 0.f);
        acc[1][0][0] = pk2(eA1.x, 0.f); acc[1][1][0] = pk2(eA1.y, 0.f);
        acc[1][2][0] = pk2(eA1.z, 0.f); acc[1][3][0] = pk2(eA1.w, 0.f);
        acc[0][0][1] = pk2(eB0.x, 0.f); acc[0][1][1] = pk2(eB0.y, 0.f);
        acc[0][2][1] = pk2(eB0.z, 0.f); acc[0][3][1] = pk2(eB0.w, 0.f);
        acc[1][0][1] = pk2(eB1.x, 0.f); acc[1][1][1] = pk2(eB1.y, 0.f);
        acc[1][2][1] = pk2(eB1.z, 0.f); acc[1][3][1] = pk2(eB1.w, 0.f);

        __syncthreads();   // psmF ready (and first-step W staging)

        // pssm contribution, packed pairs over jj (11 pairs incl. zero pad)
        {
            const ull* pp0 = (const ull*)(psmF + lane * 22);
            const ull* pp1 = (const ull*)(psmF + (lane + 32) * 22);
            #pragma unroll
            for (int tt = 0; tt < 11; tt++) {
                ull p0 = pp0[tt], p1 = pp1[tt];
                #pragma unroll
                for (int uu = 0; uu < 2; uu++) {
                    const ull* wp = (const ull*)(WpF + ((uw + uu) * 4) * 22) + tt;
                    #pragma unroll
                    for (int q = 0; q < 4; q++) {
                        ull wv = wp[q * 11];
                        FMA2(acc[uu][q][0], wv, p0);
                        FMA2(acc[uu][q][1], wv, p1);
                    }
                }
            }
        }

        // recurrent GEMM: 4 pipelined groups of 32 k-quads
        const float4* Wb0 = Wsm + (uw << 9);
        const float4* Wb1 = Wsm + ((uw + 1) << 9);
        #pragma unroll
        for (int g = 0; g < 4; g++) {
            if      (g == 0) asm volatile("cp.async.wait_group 3;" ::: "memory");
            else if (g == 1) asm volatile("cp.async.wait_group 2;" ::: "memory");
            else if (g == 2) asm volatile("cp.async.wait_group 1;" ::: "memory");
            else             asm volatile("cp.async.wait_group 0;" ::: "memory");
            __syncthreads();
            #pragma unroll 4
            for (int kq = g * 32; kq < g * 32 + 32; kq++) {
                ulonglong2 ha = *(const ulonglong2*)(hQ + (kq << 6) + lane);
                ulonglong2 hb = *(const ulonglong2*)(hQ + (kq << 6) + 32 + lane);
                const ulonglong2* W0 = (const ulonglong2*)(Wb0 + (kq << 2));
                const ulonglong2* W1 = (const ulonglong2*)(Wb1 + (kq << 2));
                #pragma unroll
                for (int q = 0; q < 4; q++) {
                    ulonglong2 wv = W0[q];
                    FMA2(acc[0][q][0], wv.x, ha.x); FMA2(acc[0][q][0], wv.y, ha.y);
                    FMA2(acc[0][q][1], wv.x, hb.x); FMA2(acc[0][q][1], wv.y, hb.y);
                }
                #pragma unroll
                for (int q = 0; q < 4; q++) {
                    ulonglong2 wv = W1[q];
                    FMA2(acc[1][q][0], wv.x, ha.x); FMA2(acc[1][q][0], wv.y, ha.y);
                    FMA2(acc[1][q][1], wv.x, hb.x); FMA2(acc[1][q][1], wv.y, hb.y);
                }
            }
        }

        // gates (torch order i,f,g,o) + publish
        float* gw = (float*)(d_gh[rb ^ 1][dir]);
        #pragma unroll
        for (int uu = 0; uu < 2; uu++) {
            int j = j0 + uu;
            #pragma unroll
            for (int bb = 0; bb < 2; bb++) {
                float2 zi = upk2(acc[uu][0][bb]);
                float2 zf = upk2(acc[uu][1][bb]);
                float2 zg = upk2(acc[uu][2][bb]);
                float2 zo = upk2(acc[uu][3][bb]);
                float ig = sigf(zi.x + zi.y);
                float fg = sigf(zf.x + zf.y);
                float gg = tanhf(zg.x + zg.y);
                float og = sigf(zo.x + zo.y);
                float c = fg * cst[uu][bb] + ig * gg;
                cst[uu][bb] = c;
                float hh = og * tanhf(c);
                int b = lane + bb * 32;
                gw[((j >> 2) * 64 + b) * 4 + (j & 3)] = hh;
                h8[b * 8 + uw + uu] = hh;
            }
        }

        __syncthreads();
        #pragma unroll
        for (int v = 0; v < 4; v++) {
            int s = tid + v * 128;
            d_hs[(size_t)(t * 64 + (s >> 3)) * 1024 + dir * 512 + ub * 8 + (s & 7)] = h8[s];
        }

        gridBarrier(r);
    }
}

// ---------------- logits + softmax + angularization: 64-row x 64-u tiled f32x2 GEMM ----------------
__global__ void __launch_bounds__(256) k_logits(const float* __restrict__ W_lin,
                                                const float* __restrict__ b_lin) {
    __shared__ float hT[64 * 66];
    __shared__ ull   wT[32 * 64];
    const int tid = threadIdx.x;
    const int row0 = blockIdx.x * 64;
    const int tu = tid & 15, tr = tid >> 4;

    ull acc[4][4];
    #pragma unroll
    for (int i = 0; i < 4; i++)
        #pragma unroll
        for (int jj = 0; jj < 4; jj++) acc[i][jj] = 0ull;

    for (int kc = 0; kc < 16; kc++) {
        #pragma unroll
        for (int v = 0; v < 4; v++) {
            int s = tid + v * 256;          // 0..1023
            int rr = s >> 4, seg = s & 15;
            float4 hv = *(const float4*)(d_hs + (size_t)(row0 + rr) * 1024 + kc * 64 + seg * 4);
            float* dst = hT + rr * 66 + seg * 4;
            dst[0] = hv.x; dst[1] = hv.y; dst[2] = hv.z; dst[3] = hv.w;
        }
        #pragma unroll
        for (int v = 0; v < 8; v++) {
            int s = tid + v * 256;          // 0..2047
            int u = s >> 5, kp = s & 31;
            ull val = 0ull;
            if (u < NLU) val = *(const ull*)(W_lin + (size_t)u * 1024 + kc * 64 + kp * 2);
            wT[kp * 64 + u] = val;
        }
        __syncthreads();
        #pragma unroll 4
        for (int kp = 0; kp < 32; kp++) {
            ulonglong2 wA = *(const ulonglong2*)(wT + kp * 64 + tu * 4);
            ulonglong2 wB = *(const ulonglong2*)(wT + kp * 64 + tu * 4 + 2);
            #pragma unroll
            for (int i = 0; i < 4; i++) {
                ull hv = *(const ull*)(hT + (tr * 4 + i) * 66 + kp * 2);
                FMA2(acc[i][0], wA.x, hv);
                FMA2(acc[i][1], wA.y, hv);
                FMA2(acc[i][2], wB.x, hv);
                FMA2(acc[i][3], wB.y, hv);
            }
        }
        __syncthreads();
    }

    // per-row softmax + angularization; row owned by 16 tu-lanes
    #pragma unroll
    for (int i = 0; i < 4; i++) {
        int row = row0 + tr * 4 + i;
        float z[4];
        #pragma unroll
        for (int jj = 0; jj < 4; jj++) {
            int u = tu * 4 + jj;
            float2 f = upk2(acc[i][jj]);
            z[jj] = (u < NLU) ? (f.x + f.y + b_lin[u]) : -3.4e38f;
        }
        float m = fmaxf(fmaxf(z[0], z[1]), fmaxf(z[2], z[3]));
        #pragma unroll
        for (int o = 8; o; o >>= 1) m = fmaxf(m, __shfl_xor_sync(0xffffffffu, m, o));
        float e[4], s = 0.f;
        #pragma unroll
        for (int jj = 0; jj < 4; jj++) { e[jj] = expf(z[jj] - m); s += e[jj]; }
        #pragma unroll
        for (int o = 8; o; o >>= 1) s += __shfl_xor_sync(0xffffffffu, s, o);
        float inv = 1.f / s;
        float sA = 0.f, cA = 0.f, sB = 0.f, cB = 0.f, sC = 0.f, cC = 0.f;
        #pragma unroll
        for (int jj = 0; jj < 4; jj++) {
            int u = tu * 4 + jj;
            if (u < NLU) {
                float p = e[jj] * inv;
                const float* tb = d_tab + u * 6;
                sA += p * tb[0]; cA += p * tb[1];
                sB += p * tb[2]; cB += p * tb[3];
                sC += p * tb[4]; cC += p * tb[5];
            }
        }
        #pragma unroll
        for (int o = 8; o; o >>= 1) {
            sA += __shfl_xor_sync(0xffffffffu, sA, o);
            cA += __shfl_xor_sync(0xffffffffu, cA, o);
            sB += __shfl_xor_sync(0xffffffffu, sB, o);
            cB += __shfl_xor_sync(0xffffffffu, cB, o);
            sC += __shfl_xor_sync(0xffffffffu, sC, o);
            cC += __shfl_xor_sync(0xffffffffu, cC, o);
        }
        if (tu == 0) {
            d_phi[row * 3 + 0] = atan2f(sA, cA);
            d_phi[row * 3 + 1] = atan2f(sB, cB);
            d_phi[row * 3 + 2] = atan2f(sC, cC);
        }
    }
}

// ---------------- NeRF chain extension (thread per batch) ----------------
__global__ void k_geom(float* __restrict__ out) {
    int b = threadIdx.x;
    if (b >= NB) return;
    const float BL[3] = {132.868f, 145.801f, 152.326f};
    const float BA[3] = {2.028f, 2.124f, 1.941f};
    float cT[3], sT[3];
    #pragma unroll
    for (int jj = 0; jj < 3; jj++) sincosf(BA[jj], &sT[jj], &cT[jj]);

    float Ax = 1.f, Ay = 0.f, Az = 0.f;
    float Bx = 0.f, By = 1.f, Bz = 0.f;
    float Cx = 0.f, Cy = 0.f, Cz = 1.f;
    #pragma unroll
    for (int r = 0; r < 3; r++)
        #pragma unroll
        for (int c = 0; c < 3; c++)
            out[((size_t)r * 64 + b) * 3 + c] = (r == c) ? 1.f : 0.f;

    for (int i = 0; i < NL; i++) {
        #pragma unroll
        for (int jj = 0; jj < 3; jj++) {
            float P = d_phi[((size_t)i * 64 + b) * 3 + jj];
            float sp, cp;
            sincosf(P, &sp, &cp);
            float D2x = -BL[jj] * cT[jj];
            float D2y =  BL[jj] * cp * sT[jj];
            float D2z =  BL[jj] * sp * sT[jj];
            float bcx = Cx - Bx, bcy = Cy - By, bcz = Cz - Bz;
            float il = 1.f / sqrtf(bcx * bcx + bcy * bcy + bcz * bcz);
            bcx *= il; bcy *= il; bcz *= il;
            float abx = Bx - Ax, aby = By - Ay, abz = Bz - Az;
            float nx = aby * bcz - abz * bcy;
            float ny = abz * bcx - abx * bcz;
            float nz = abx * bcy - aby * bcx;
            float iln = 1.f / sqrtf(nx * nx + ny * ny + nz * nz);
            nx *= iln; ny *= iln; nz *= iln;
            float mx = ny * bcz - nz * bcy;
            float my = nz * bcx - nx * bcz;
            float mz = nx * bcy - ny * bcx;
            float Dx = D2x * bcx + D2y * mx + D2z * nx + Cx;
            float Dy = D2x * bcy + D2y * my + D2z * ny + Cy;
            float Dz = D2x * bcz + D2y * mz + D2z * nz + Cz;
            size_t rw = (size_t)(3 + i * 3 + jj) * 64 + b;
            out[rw * 3 + 0] = Dx; out[rw * 3 + 1] = Dy; out[rw * 3 + 2] = Dz;
            Ax = Bx; Ay = By; Az = Bz;
            Bx = Cx; By = Cy; Bz = Cz;
            Cx = Dx; Cy = Dy; Cz = Dz;
        }
    }
}

extern "C" void kernel_launch(void* const* d_in, const int* in_sizes, int n_in,
                              void* d_out, int out_size) {
    const int*   seq      = (const int*)d_in[0];
    const float* pssm     = (const float*)d_in[1];
    // d_in[2] = length (unused: all full-length)
    const float* embed    = (const float*)d_in[3];
    const float* Wih_f    = (const float*)d_in[4];
    const float* Whh_f    = (const float*)d_in[5];
    const float* bih_f    = (const float*)d_in[6];
    const float* bhh_f    = (const float*)d_in[7];
    const float* Wih_b    = (const float*)d_in[8];
    const float* Whh_b    = (const float*)d_in[9];
    const float* bih_b    = (const float*)d_in[10];
    const float* bhh_b    = (const float*)d_in[11];
    const float* W_lin    = (const float*)d_in[12];
    const float* b_lin    = (const float*)d_in[13];
    const float* alphabet = (const float*)d_in[14];
    float* out = (float*)d_out;

    cudaFuncSetAttribute(k_lstm, cudaFuncAttributeMaxDynamicSharedMemorySize, SMEM_LSTM);

    k_init<<<128, 256>>>(alphabet);
    k_embed<<<512, 256>>>(embed, Wih_f, bih_f, bhh_f, Wih_b, bih_b, bhh_b);
    k_lstm<<<NCTA_LSTM, 128, SMEM_LSTM>>>(seq, pssm, Whh_f, Whh_b, Wih_f, Wih_b);
    k_logits<<<NL * NB / 64, 256>>>(W_lin, b_lin);
    k_geom<<<1, 64>>>(out);
}